// round 11
// baseline (speedup 1.0000x reference)
#include <cuda_runtime.h>
#include <cuda_bf16.h>
#include <cstdint>

#define BATCH 256
#define NPOS 4
#define NNEG 1024
#define DIM 512
#define ROW4 (DIM / 4)                            // 128 float4 per row
#define CHUNKS 8
#define ROWS_PER_CHUNK (NNEG / CHUNKS)            // 128
#define WARPS_B 8
#define NITEMS (BATCH * CHUNKS)                   // 2048
#define NSTAGE 4
#define ROWS_PER_STAGE 8
#define STAGE_BYTES (ROWS_PER_STAGE * DIM * 4)    // 16384
#define STAGE_F4 (STAGE_BYTES / 16)               // 1024 float4
#define NITER (ROWS_PER_CHUNK / ROWS_PER_STAGE)   // 16
#define SMEM_DYN (NSTAGE * STAGE_BYTES)           // 65536
#define EPS_F 1e-8f
#define INV_T 10.0f

// Scratch (device allocation forbidden) — fully rewritten each launch.
__device__ float g_pos_sim[BATCH * NPOS];
__device__ float g_exp_part[NITEMS];
__device__ int4  g_cnt_part[NITEMS];
__device__ unsigned int g_ticket = 0;   // reset by the finalizing block each launch

// ---------------------------------------------------------------------------
// PTX helpers: mbarrier + 1D bulk async copy (UBLKCP).  No tensormap needed.
// ---------------------------------------------------------------------------
__device__ __forceinline__ uint32_t smem_u32(const void* p) {
    uint32_t a;
    asm("{ .reg .u64 t; cvta.to.shared.u64 t, %1; cvt.u32.u64 %0, t; }" : "=r"(a) : "l"(p));
    return a;
}
#define MBAR_INIT(addr, cnt) \
    asm volatile("mbarrier.init.shared.b64 [%0], %1;" :: "r"(addr), "r"(cnt) : "memory")
#define MBAR_EXPECT_TX(addr, bytes) \
    asm volatile("mbarrier.arrive.expect_tx.shared.b64 _, [%0], %1;" :: "r"(addr), "r"(bytes) : "memory")
#define BULK_G2S(dst_smem, src_gmem, bytes, mbar) \
    asm volatile("cp.async.bulk.shared::cta.global.mbarrier::complete_tx::bytes [%0], [%1], %2, [%3];" \
                 :: "r"(dst_smem), "l"(src_gmem), "r"(bytes), "r"(mbar) : "memory")

__device__ __forceinline__ void mbar_wait(uint32_t mbar, uint32_t parity) {
    uint32_t done;
    asm volatile(
        "{\n\t.reg .pred p;\n\t"
        "mbarrier.try_wait.parity.acquire.cta.shared::cta.b64 p, [%1], %2;\n\t"
        "selp.b32 %0, 1, 0, p;\n\t}"
        : "=r"(done) : "r"(mbar), "r"(parity) : "memory");
    if (!done) {
        asm volatile(
            "{\n\t.reg .pred P1;\n\t"
            "W_%=:\n\t"
            "mbarrier.try_wait.parity.acquire.cta.shared::cta.b64 P1, [%0], %1, 0x989680;\n\t"
            "@P1 bra W_DONE_%=;\n\t"
            "bra.uni W_%=;\n\t"
            "W_DONE_%=:\n\t}"
            :: "r"(mbar), "r"(parity) : "memory");
    }
}

// ---------------------------------------------------------------------------
// Bulk-copy streaming kernel.  One block per (b, chunk of 128 negative rows).
//   Producer (thread 0): 4-stage ring of 16 KB cp.async.bulk fills — 64 KB in
//   flight per CTA at zero register / zero per-lane issue cost.
//   Consumers: warp w processes row w of each stage from SMEM (4 LDS.128 per
//   lane, conflict-free), dot+sumsq vs register anchor, 5-level shuffle, tail.
//   Stage recycling via __syncthreads (all warps done -> thread 0 refills).
//   Finalization: global ticket; last block folds all partials determinis-
//   tically and writes the scalar loss.
// ---------------------------------------------------------------------------
extern __shared__ float4 s_stage[];   // NSTAGE * 1024 float4 = 64 KB

__global__ void __launch_bounds__(256, 3)
rrl_bulk_kernel(const float* __restrict__ anchor,
                const float* __restrict__ positives,
                const float* __restrict__ negatives,
                float* __restrict__ out) {
    const int item  = blockIdx.x;
    const int b     = item >> 3;
    const int chunk = item & 7;
    const int w     = threadIdx.x >> 5;
    const int lane  = threadIdx.x & 31;

    __shared__ __align__(8) uint64_t s_mbar[NSTAGE];
    __shared__ float s_pos[NPOS];
    __shared__ float s_rinv;
    __shared__ float s_exp[WARPS_B];
    __shared__ int   s_cnt[WARPS_B][NPOS];
    __shared__ int   s_last;

    const uint32_t mbar0  = smem_u32(&s_mbar[0]);
    const uint32_t stage0 = smem_u32(&s_stage[0]);
    const char* src_base = reinterpret_cast<const char*>(
        negatives + ((size_t)b * NNEG + chunk * ROWS_PER_CHUNK) * DIM);

    // ---- producer init + prime the ring (thread 0 only) ----
    if (threadIdx.x == 0) {
#pragma unroll
        for (int s = 0; s < NSTAGE; s++) MBAR_INIT(mbar0 + 8 * s, 1);
        // make inits visible to the async proxy before the first bulk ops
        asm volatile("fence.proxy.async.shared::cta;" ::: "memory");
#pragma unroll
        for (int s = 0; s < NSTAGE; s++) {
            MBAR_EXPECT_TX(mbar0 + 8 * s, STAGE_BYTES);
            BULK_G2S(stage0 + s * STAGE_BYTES, src_base + (size_t)s * STAGE_BYTES,
                     STAGE_BYTES, mbar0 + 8 * s);
        }
    }

    // ---- prologue (overlapped with the in-flight bulk copies) ----
    const float4* a4 = reinterpret_cast<const float4*>(anchor + (size_t)b * DIM);
    float4 af[4];
#pragma unroll
    for (int k = 0; k < 4; k++) af[k] = a4[lane + 32 * k];

    if (w < NPOS) {
        const float4* p4 =
            reinterpret_cast<const float4*>(positives + ((size_t)b * NPOS + w) * DIM);
        float dot = 0.f, sqa = 0.f, sqp = 0.f;
#pragma unroll
        for (int k = 0; k < 4; k++) {
            float4 pv = p4[lane + 32 * k];
            dot += af[k].x * pv.x + af[k].y * pv.y + af[k].z * pv.z + af[k].w * pv.w;
            sqa += af[k].x * af[k].x + af[k].y * af[k].y + af[k].z * af[k].z + af[k].w * af[k].w;
            sqp += pv.x * pv.x + pv.y * pv.y + pv.z * pv.z + pv.w * pv.w;
        }
#pragma unroll
        for (int o = 16; o; o >>= 1) {
            dot += __shfl_xor_sync(0xffffffffu, dot, o);
            sqa += __shfl_xor_sync(0xffffffffu, sqa, o);
            sqp += __shfl_xor_sync(0xffffffffu, sqp, o);
        }
        if (lane == 0) {
            const float na = sqrtf(sqa);
            const float sim = dot / fmaxf(na * sqrtf(sqp), EPS_F);
            s_pos[w] = sim;
            if (w == 0) s_rinv = 1.0f / na;
            if (chunk == 0) g_pos_sim[b * NPOS + w] = sim;
        }
    }
    __syncthreads();   // publishes s_pos/s_rinv AND mbarrier inits to all threads

    const float rinv_a = s_rinv;
    const float t0 = s_pos[0], t1 = s_pos[1], t2 = s_pos[2], t3 = s_pos[3];

    float sum_exp = 0.f;
    int c0 = 0, c1 = 0, c2 = 0, c3 = 0;

    // ---- staged consumption loop ----
    for (int i = 0; i < NITER; i++) {
        const int st = i & (NSTAGE - 1);
        const uint32_t ph = (i >> 2) & 1;

        mbar_wait(mbar0 + 8 * st, ph);

        // warp w consumes row w of this stage: 4 LDS.128 per lane, conflict-free
        const float4* rp = s_stage + st * STAGE_F4 + w * ROW4;
        float d0 = 0.f, d1 = 0.f, d2 = 0.f, d3 = 0.f;
        float q0 = 0.f, q1 = 0.f, q2 = 0.f, q3 = 0.f;
        {
            const float4 x0 = rp[lane +  0];
            const float4 x1 = rp[lane + 32];
            const float4 x2 = rp[lane + 64];
            const float4 x3 = rp[lane + 96];
            d0 = af[0].x * x0.x + af[0].y * x0.y + af[0].z * x0.z + af[0].w * x0.w;
            d1 = af[1].x * x1.x + af[1].y * x1.y + af[1].z * x1.z + af[1].w * x1.w;
            d2 = af[2].x * x2.x + af[2].y * x2.y + af[2].z * x2.z + af[2].w * x2.w;
            d3 = af[3].x * x3.x + af[3].y * x3.y + af[3].z * x3.z + af[3].w * x3.w;
            q0 = x0.x * x0.x + x0.y * x0.y + x0.z * x0.z + x0.w * x0.w;
            q1 = x1.x * x1.x + x1.y * x1.y + x1.z * x1.z + x1.w * x1.w;
            q2 = x2.x * x2.x + x2.y * x2.y + x2.z * x2.z + x2.w * x2.w;
            q3 = x3.x * x3.x + x3.y * x3.y + x3.z * x3.z + x3.w * x3.w;
        }
        float dot = (d0 + d1) + (d2 + d3);
        float sq  = (q0 + q1) + (q2 + q3);

#pragma unroll
        for (int o = 16; o; o >>= 1) {
            dot += __shfl_xor_sync(0xffffffffu, dot, o);
            sq  += __shfl_xor_sync(0xffffffffu, sq, o);
        }

        const float sim = dot * (rinv_a * rsqrtf(fmaxf(sq, EPS_F * EPS_F)));
        sum_exp += __expf(sim * INV_T);
        c0 += (sim > t0);
        c1 += (sim > t1);
        c2 += (sim > t2);
        c3 += (sim > t3);

        // recycle: all warps done with stage st -> thread 0 refills it
        __syncthreads();
        if (threadIdx.x == 0 && i + NSTAGE < NITER) {
            MBAR_EXPECT_TX(mbar0 + 8 * st, STAGE_BYTES);
            BULK_G2S(stage0 + st * STAGE_BYTES,
                     src_base + (size_t)(i + NSTAGE) * STAGE_BYTES,
                     STAGE_BYTES, mbar0 + 8 * st);
        }
    }

    // ---- per-item fold ----
    if (lane == 0) {
        s_exp[w]    = sum_exp;
        s_cnt[w][0] = c0; s_cnt[w][1] = c1; s_cnt[w][2] = c2; s_cnt[w][3] = c3;
    }
    __syncthreads();
    if (threadIdx.x == 0) {
        float se = 0.f;
        int k0 = 0, k1 = 0, k2 = 0, k3 = 0;
#pragma unroll
        for (int j = 0; j < WARPS_B; j++) {
            se += s_exp[j];
            k0 += s_cnt[j][0]; k1 += s_cnt[j][1]; k2 += s_cnt[j][2]; k3 += s_cnt[j][3];
        }
        g_exp_part[item] = se;
        g_cnt_part[item] = make_int4(k0, k1, k2, k3);
        __threadfence();                       // partials visible before ticket
        const unsigned int t = atomicAdd(&g_ticket, 1u);
        s_last = (t == NITEMS - 1u) ? 1 : 0;
    }
    __syncthreads();

    // ---- last block finalizes (deterministic fixed-order fold) ----
    if (s_last) {
        const int bb = threadIdx.x;            // thread = batch index

        float se = 0.f;
        int cnt[NPOS] = {0, 0, 0, 0};
#pragma unroll
        for (int c = 0; c < CHUNKS; c++) {
            const int idx = bb * CHUNKS + c;
            se += g_exp_part[idx];
            const int4 k = g_cnt_part[idx];
            cnt[0] += k.x; cnt[1] += k.y; cnt[2] += k.z; cnt[3] += k.w;
        }

        float ps[NPOS], ep[NPOS];
        float denom = se;
#pragma unroll
        for (int p = 0; p < NPOS; p++) {
            ps[p] = g_pos_sim[bb * NPOS + p];
            ep[p] = expf(ps[p] * INV_T);
            denom += ep[p];
        }

        float err = 0.f, psum = 0.f;
#pragma unroll
        for (int p = 0; p < NPOS; p++) {
            int rank = cnt[p];
#pragma unroll
            for (int q = 0; q < NPOS; q++) {
                if (ps[q] > ps[p]) rank++;
                else if (q < p && ps[q] == ps[p]) rank++;
            }
            err  += (ep[p] / denom) / (float)(rank + 1);
            psum += ps[p];
        }

        __shared__ float s_err[256];
        __shared__ float s_psum[256];
        s_err[bb]  = err;
        s_psum[bb] = psum;
        __syncthreads();
        for (int off = 128; off; off >>= 1) {
            if (bb < off) {
                s_err[bb]  += s_err[bb + off];
                s_psum[bb] += s_psum[bb + off];
            }
            __syncthreads();
        }
        if (bb == 0) {
            out[0] = -s_err[0] / (float)BATCH +
                     0.3f * (1.0f - s_psum[0] / (float)(BATCH * NPOS));
            g_ticket = 0;                      // re-arm for next (graph) replay
        }
    }
}

// ---------------------------------------------------------------------------
extern "C" void kernel_launch(void* const* d_in, const int* in_sizes, int n_in,
                              void* d_out, int out_size) {
    const float* anchor    = (const float*)d_in[0];
    const float* positives = (const float*)d_in[1];
    const float* negatives = (const float*)d_in[2];

    // 64 KB dynamic SMEM opt-in (idempotent; not a stream op, capture-legal)
    cudaFuncSetAttribute(rrl_bulk_kernel,
                         cudaFuncAttributeMaxDynamicSharedMemorySize, SMEM_DYN);

    rrl_bulk_kernel<<<NITEMS, 256, SMEM_DYN>>>(anchor, positives, negatives,
                                               (float*)d_out);
}